// round 12
// baseline (speedup 1.0000x reference)
#include <cuda_runtime.h>
#include <cuda_bf16.h>
#include <cstdint>
#include <math.h>

#define D_MODEL 2048
#define SEQ     2048
#define BATCH   2
#define NHEAD   16
#define HD      128
#define MROWS   (BATCH*SEQ)   // 4096

// Packed GEMM tile-image geometry (matches GEMM smem layout exactly)
#define PADB     80
#define AMAT     (128 * PADB)          // 10240
#define BLKB     (2 * AMAT)            // 20480: hi||lo
#define STAGEB   (2 * BLKB)            // 40960: A + B

// Packed flash image geometry
#define FL_STRIDE 272
#define FL_MAT    (64 * FL_STRIDE)      // 17408
#define FL_STAGE  (4 * FL_MAT)          // 69632: kh,kl,vh,vl
#define FL_QMAT   (128 * FL_STRIDE)     // 34816
#define FL_QBLK   (2 * FL_QMAT)         // 69632
#define FL_SMEM   (2 * FL_STAGE + 32)

#define GEMM_SMEM (2 * STAGEB + 16)

// ---------------------------------------------------------------------------
// Scratch (__device__ globals: allocation-free rule)
// ---------------------------------------------------------------------------
__device__ float g_q[MROWS * D_MODEL];
__device__ float g_k[MROWS * D_MODEL];
__device__ float g_v[MROWS * D_MODEL];

__device__ __align__(128) unsigned char g_xpack[32 * 64 * BLKB];
__device__ __align__(128) unsigned char g_apack[32 * 64 * BLKB];
__device__ __align__(128) unsigned char g_wpack[64 * 64 * BLKB];
__device__ __align__(128) unsigned char g_qpack[32 * 16 * FL_QBLK];   // [bh][qt]
__device__ __align__(128) unsigned char g_kvpack[32 * 32 * FL_STAGE]; // [bh][kt]

// ---------------------------------------------------------------------------
// PTX helpers (plain sm_103: no tcgen05; bulk-copy + mbarrier are sm_90 base)
// ---------------------------------------------------------------------------
__device__ __forceinline__ uint32_t smem_u32(const void* p) {
    uint32_t a;
    asm("{ .reg .u64 t; cvta.to.shared.u64 t, %1; cvt.u32.u64 %0, t; }" : "=r"(a) : "l"(p));
    return a;
}
__device__ __forceinline__ void cp16(uint32_t dst, const void* src) {
    asm volatile("cp.async.cg.shared.global [%0], [%1], 16;" :: "r"(dst), "l"(src) : "memory");
}
#define CP_COMMIT() asm volatile("cp.async.commit_group;" ::: "memory")
#define CP_WAIT(n)  asm volatile("cp.async.wait_group %0;" :: "n"(n) : "memory")

#define MBAR_INIT(a, n) asm volatile("mbarrier.init.shared.b64 [%0], %1;" :: "r"(a), "r"(n) : "memory")
#define MBAR_EXPECT(a, n) \
    asm volatile("mbarrier.arrive.expect_tx.shared.b64 _, [%0], %1;" :: "r"(a), "r"(n) : "memory")
#define MBAR_WAIT(a, ph) do { \
    uint32_t _m = (a), _p = (ph), _d; \
    asm volatile("{\n\t.reg .pred p;\n\tmbarrier.try_wait.parity.acquire.cta.shared::cta.b64 p, [%1], %2;\n\tselp.b32 %0,1,0,p;\n\t}" \
        : "=r"(_d) : "r"(_m), "r"(_p) : "memory"); \
    if (!_d) { \
        asm volatile("{\n\t.reg .pred P1;\n\tWL%=: mbarrier.try_wait.parity.acquire.cta.shared::cta.b64 P1, [%0], %1, 0x989680;\n\t@P1 bra.uni WD%=;\n\tbra.uni WL%=;\n\tWD%=:\n\t}" \
            :: "r"(_m), "r"(_p) : "memory"); \
    } } while (0)

#define BULK_G2S(dst, src, bytes, mbar) \
    asm volatile("cp.async.bulk.shared::cta.global.mbarrier::complete_tx::bytes [%0], [%1], %2, [%3];" \
        :: "r"(dst), "l"(src), "r"(bytes), "r"(mbar) : "memory")

#define LDSM_X4(r, addr) \
    asm volatile("ldmatrix.sync.aligned.m8n8.x4.shared.b16 {%0,%1,%2,%3}, [%4];" \
        : "=r"((r)[0]), "=r"((r)[1]), "=r"((r)[2]), "=r"((r)[3]) : "r"(addr))
#define LDSM_T_X4(r, addr) \
    asm volatile("ldmatrix.sync.aligned.m8n8.x4.trans.shared.b16 {%0,%1,%2,%3}, [%4];" \
        : "=r"((r)[0]), "=r"((r)[1]), "=r"((r)[2]), "=r"((r)[3]) : "r"(addr))

#define MMA_BF16(c, a, b) \
    asm volatile("mma.sync.aligned.m16n8k16.row.col.f32.bf16.bf16.f32 " \
        "{%0,%1,%2,%3}, {%4,%5,%6,%7}, {%8,%9}, {%0,%1,%2,%3};" \
        : "+f"((c)[0]), "+f"((c)[1]), "+f"((c)[2]), "+f"((c)[3]) \
        : "r"((a)[0]), "r"((a)[1]), "r"((a)[2]), "r"((a)[3]), "r"((b)[0]), "r"((b)[1]))

__device__ __forceinline__ void split2(float a, float b, uint32_t& hi, uint32_t& lo) {
    __nv_bfloat16 ha = __float2bfloat16(a), hb = __float2bfloat16(b);
    float ra = a - __bfloat162float(ha), rb = b - __bfloat162float(hb);
    __nv_bfloat16 la = __float2bfloat16(ra), lb = __float2bfloat16(rb);
    hi = (uint32_t)__bfloat16_as_ushort(ha) | ((uint32_t)__bfloat16_as_ushort(hb) << 16);
    lo = (uint32_t)__bfloat16_as_ushort(la) | ((uint32_t)__bfloat16_as_ushort(lb) << 16);
}

// ---------------------------------------------------------------------------
// x (fp32 row-major) -> packed hi/lo tile images
// ---------------------------------------------------------------------------
__global__ void split_e_pack(const float* __restrict__ in, unsigned char* __restrict__ pack) {
    int t = blockIdx.x * blockDim.x + threadIdx.x;
    if (t >= MROWS * D_MODEL / 8) return;
    int ch  = t & 3;
    int row = (t >> 2) & 127;
    int c   = (t >> 9) & 63;
    int tm  = t >> 15;

    const float* src = in + ((size_t)(tm * 128 + row)) * D_MODEL + c * 32 + ch * 8;
    float4 v0 = *(const float4*)src;
    float4 v1 = *(const float4*)(src + 4);
    uint32_t h[4], l[4];
    split2(v0.x, v0.y, h[0], l[0]);
    split2(v0.z, v0.w, h[1], l[1]);
    split2(v1.x, v1.y, h[2], l[2]);
    split2(v1.z, v1.w, h[3], l[3]);

    unsigned char* blk = pack + ((size_t)(tm * 64 + c)) * BLKB;
    *(uint4*)(blk + row * PADB + ch * 16)        = make_uint4(h[0], h[1], h[2], h[3]);
    *(uint4*)(blk + AMAT + row * PADB + ch * 16) = make_uint4(l[0], l[1], l[2], l[3]);
}

// W[K,N] fp32 -> transposed packed hi/lo tile images
__global__ void split_t_pack(const float* __restrict__ in, unsigned char* __restrict__ pack,
                             int wbase) {
    __shared__ float t[32][33];
    int tx = threadIdx.x, ty = threadIdx.y;
    int bn = blockIdx.x, bk = blockIdx.y;
    #pragma unroll
    for (int j = 0; j < 4; j++) {
        int k = bk * 32 + ty + j * 8;
        t[ty + j * 8][tx] = in[(size_t)k * D_MODEL + bn * 32 + tx];
    }
    __syncthreads();
    #pragma unroll
    for (int j = 0; j < 4; j++) {
        int n = bn * 32 + ty + j * 8;
        int k = bk * 32 + tx;
        float v = t[tx][ty + j * 8];
        __nv_bfloat16 hb = __float2bfloat16(v);
        __nv_bfloat16 lb = __float2bfloat16(v - __bfloat162float(hb));
        size_t boff = ((size_t)((wbase + (n >> 7)) * 64 + bk)) * BLKB
                    + (uint32_t)(n & 127) * PADB + ((k & 31) >> 3) * 16 + (k & 7) * 2;
        *(__nv_bfloat16*)(pack + boff)        = hb;
        *(__nv_bfloat16*)(pack + boff + AMAT) = lb;
    }
}

// ---------------------------------------------------------------------------
// HMMA GEMM with bulk-copy loads + L2 rasterization swizzle (group 16).
// CTA 128x128, BK=32, 2-stage, occ 2. (round-9-proven pipeline)
// ---------------------------------------------------------------------------
__global__ __launch_bounds__(256, 2)
void gemm_hmma(const unsigned char* __restrict__ Apack,
               const unsigned char* __restrict__ Wpack, int wbase,
               float* __restrict__ C0, float* __restrict__ C1, float* __restrict__ C2) {
    extern __shared__ char smem[];
    const uint32_t sb = smem_u32(smem);
    const int tid  = threadIdx.x;
    const int wid  = tid >> 5;
    const int lane = tid & 31;

    // swizzle: within a group of 16 N-tiles, tileM varies fastest
    const int bid = blockIdx.x + (int)gridDim.x * blockIdx.y;
    const int MT  = gridDim.y;            // 32
    const int gsz = 16 * MT;              // 512
    const int tileM = (bid % gsz) % MT;
    const int tileN = (bid / gsz) * 16 + (bid % gsz) / MT;

    float* C = (tileN < 16) ? C0 : ((tileN < 32) ? C1 : C2);
    const int nloc = tileN & 15;

    const int m0w = (wid >> 2) * 64;
    const int n0w = (wid & 3) * 32;

    const uint32_t mb0 = sb + 2 * STAGEB;
    if (tid == 0) { MBAR_INIT(mb0, 1); MBAR_INIT(mb0 + 8, 1); }
    __syncthreads();

    auto issue_load = [&](int s, int c) {
        if (tid == 0) {
            uint32_t mb = mb0 + s * 8;
            MBAR_EXPECT(mb, (uint32_t)STAGEB);
            BULK_G2S(sb + s * STAGEB,
                     Apack + ((size_t)(tileM * 64 + c)) * BLKB, (uint32_t)BLKB, mb);
            BULK_G2S(sb + s * STAGEB + BLKB,
                     Wpack + ((size_t)((wbase + tileN) * 64 + c)) * BLKB, (uint32_t)BLKB, mb);
        }
    };

    float acc[4][4][4];
    #pragma unroll
    for (int i = 0; i < 4; i++)
        #pragma unroll
        for (int j = 0; j < 4; j++)
            #pragma unroll
            for (int r = 0; r < 4; r++) acc[i][j][r] = 0.f;

    issue_load(0, 0);
    issue_load(1, 1);

    const int NCH = D_MODEL / 32;   // 64
    for (int c = 0; c < NCH; c++) {
        const int s = c & 1;
        MBAR_WAIT(mb0 + s * 8, (c >> 1) & 1);

        const uint32_t st = sb + s * STAGEB;
        #pragma unroll
        for (int ks = 0; ks < 2; ks++) {
            uint32_t ah[4][4], al[4][4];
            const uint32_t arow = (lane & 15);
            const uint32_t akb  = (ks * 16 + (lane >> 4) * 8) * 2;
            #pragma unroll
            for (int mt = 0; mt < 4; mt++) {
                uint32_t ra = st + (m0w + mt * 16 + arow) * PADB + akb;
                LDSM_X4(ah[mt], ra);
                LDSM_X4(al[mt], ra + AMAT);
            }
            const uint32_t brow = (lane & 7) + ((lane >> 4) & 1) * 8;
            const uint32_t bkb  = (ks * 16 + ((lane >> 3) & 1) * 8) * 2;
            #pragma unroll
            for (int np = 0; np < 2; np++) {
                uint32_t rb = st + BLKB + (n0w + np * 16 + brow) * PADB + bkb;
                uint32_t bh4[4], bl4[4];
                LDSM_X4(bh4, rb);
                LDSM_X4(bl4, rb + AMAT);
                #pragma unroll
                for (int half = 0; half < 2; half++) {
                    const int nt = np * 2 + half;
                    uint32_t* bh = bh4 + half * 2;
                    uint32_t* bl = bl4 + half * 2;
                    #pragma unroll
                    for (int mt = 0; mt < 4; mt++) {
                        MMA_BF16(acc[mt][nt], ah[mt], bh);
                        MMA_BF16(acc[mt][nt], ah[mt], bl);
                        MMA_BF16(acc[mt][nt], al[mt], bh);
                    }
                }
            }
        }
        __syncthreads();
        if (c + 2 < NCH) issue_load(s, c + 2);
    }

    float* cbase = C + (size_t)tileM * 128 * D_MODEL + nloc * 128;
    const int rq = lane >> 2;
    const int cq = (lane & 3) * 2;
    #pragma unroll
    for (int mt = 0; mt < 4; mt++) {
        #pragma unroll
        for (int nt = 0; nt < 4; nt++) {
            int row = m0w + mt * 16 + rq;
            int col = n0w + nt * 8 + cq;
            *(float2*)(cbase + (size_t)row * D_MODEL + col) =
                make_float2(acc[mt][nt][0], acc[mt][nt][1]);
            *(float2*)(cbase + (size_t)(row + 8) * D_MODEL + col) =
                make_float2(acc[mt][nt][2], acc[mt][nt][3]);
        }
    }
}

// ---------------------------------------------------------------------------
// RoPE + split directly into packed flash images (Q scaled by rsqrt*log2e)
// ---------------------------------------------------------------------------
__global__ void rope_split(const float* __restrict__ q, const float* __restrict__ k,
                           const float* __restrict__ v,
                           unsigned char* __restrict__ qpack,
                           unsigned char* __restrict__ kvpack) {
    const int total = MROWS * NHEAD * (HD / 2);
    int idx = blockIdx.x * blockDim.x + threadIdx.x;
    if (idx >= total) return;
    int u   = idx & 63;
    int h   = (idx >> 6) & 15;
    int row = idx >> 10;          // 0..4095
    int s   = row & (SEQ - 1);
    int b   = row >> 11;
    int bh  = b * NHEAD + h;

    float inv_freq = exp2f(-13.287712379549449f * ((float)(2 * u) * (1.0f / 128.0f)));
    float ang = (float)s * inv_freq;
    float sn, cs;
    sincosf(ang, &sn, &cs);

    const float SCF = 0.08838834764831845f * 1.4426950408889634f;

    size_t off = (size_t)row * D_MODEL + h * HD + 2 * u;
    float2 qv = *(const float2*)(q + off);
    float2 kv = *(const float2*)(k + off);
    float2 vv = *(const float2*)(v + off);

    float q0 = (qv.x * cs - qv.y * sn) * SCF;
    float q1 = (qv.x * sn + qv.y * cs) * SCF;
    float k0 = kv.x * cs - kv.y * sn;
    float k1 = kv.x * sn + kv.y * cs;

    uint32_t hi, lo;

    {
        int qt = s >> 7, qrow = s & 127;
        size_t base = ((size_t)(bh * 16 + qt)) * FL_QBLK + (uint32_t)qrow * FL_STRIDE + u * 4;
        split2(q0, q1, hi, lo);
        *(uint32_t*)(qpack + base)           = hi;
        *(uint32_t*)(qpack + base + FL_QMAT) = lo;
    }
    {
        int kt = s >> 6, krow = s & 63;
        size_t base = ((size_t)(bh * 32 + kt)) * FL_STAGE + (uint32_t)krow * FL_STRIDE + u * 4;
        split2(k0, k1, hi, lo);
        *(uint32_t*)(kvpack + base)              = hi;
        *(uint32_t*)(kvpack + base + FL_MAT)     = lo;
        split2(vv.x, vv.y, hi, lo);
        *(uint32_t*)(kvpack + base + 2 * FL_MAT) = hi;
        *(uint32_t*)(kvpack + base + 3 * FL_MAT) = lo;
    }
}

// ---------------------------------------------------------------------------
// HMMA flash attention with bulk-copy loads (round-9-proven).
// ---------------------------------------------------------------------------
__global__ __launch_bounds__(256, 1)
void flash_hmma(const unsigned char* __restrict__ qpack,
                const unsigned char* __restrict__ kvpack,
                unsigned char* __restrict__ apack) {
    extern __shared__ char smem[];
    const uint32_t sb = smem_u32(smem);
    const int tid  = threadIdx.x;
    const int w    = tid >> 5;
    const int lane = tid & 31;
    const int qt = (int)gridDim.x - 1 - (int)blockIdx.x;   // longest-first
    const int bh = blockIdx.y;
    const int b  = bh >> 4;
    const int h  = bh & 15;

    const int q0 = qt * 128;
    const int C  = 2 * qt + 2;

    const uint32_t qsm = sb + FL_STAGE;
    const uint32_t mb0 = sb + 2 * FL_STAGE;

    if (tid == 0) { MBAR_INIT(mb0, 1); MBAR_INIT(mb0 + 8, 1); MBAR_INIT(mb0 + 16, 1); }
    __syncthreads();

    const unsigned char* kvbase = kvpack + ((size_t)bh * 32) * FL_STAGE;

    if (tid == 0) {
        MBAR_EXPECT(mb0 + 16, (uint32_t)FL_QBLK);
        BULK_G2S(qsm, qpack + ((size_t)(bh * 16 + qt)) * FL_QBLK, (uint32_t)FL_QBLK, mb0 + 16);
        MBAR_EXPECT(mb0, (uint32_t)FL_STAGE);
        BULK_G2S(sb, kvbase, (uint32_t)FL_STAGE, mb0);
    }

    MBAR_WAIT(mb0 + 16, 0);
    uint32_t fqh[8][4], fql[8][4];
    #pragma unroll
    for (int kk = 0; kk < 8; kk++) {
        uint32_t ra = qsm + (w * 16 + (lane & 15)) * FL_STRIDE + (kk * 16 + (lane >> 4) * 8) * 2;
        LDSM_X4(fqh[kk], ra);
        LDSM_X4(fql[kk], ra + FL_QMAT);
    }
    __syncthreads();
    if (1 < C && tid == 0) {
        MBAR_EXPECT(mb0 + 8, (uint32_t)FL_STAGE);
        BULK_G2S(sb + FL_STAGE, kvbase + FL_STAGE, (uint32_t)FL_STAGE, mb0 + 8);
    }

    float o[16][4];
    #pragma unroll
    for (int nt = 0; nt < 16; nt++)
        #pragma unroll
        for (int r = 0; r < 4; r++) o[nt][r] = 0.f;
    float m0 = -1e30f, m1 = -1e30f, l0 = 0.f, l1 = 0.f;

    const int r0 = q0 + w * 16 + (lane >> 2);
    const int r1 = r0 + 8;

    for (int c = 0; c < C; c++) {
        const int s = c & 1;
        MBAR_WAIT(mb0 + s * 8, (c >> 1) & 1);
        const uint32_t st = sb + s * FL_STAGE;

        const bool skip = (64 * c > q0 + w * 16 + 15);
        if (!skip) {
            float s8[8][4];
            #pragma unroll
            for (int t = 0; t < 8; t++)
                #pragma unroll
                for (int r = 0; r < 4; r++) s8[t][r] = 0.f;

            #pragma unroll
            for (int kk = 0; kk < 8; kk++) {
                #pragma unroll
                for (int np = 0; np < 4; np++) {
                    uint32_t rb = st + (np * 16 + (lane & 7) + ((lane >> 4) & 1) * 8) * FL_STRIDE
                                     + (((lane >> 3) & 1) * 8 + kk * 16) * 2;
                    uint32_t bh4[4], bl4[4];
                    LDSM_X4(bh4, rb);
                    LDSM_X4(bl4, rb + FL_MAT);
                    MMA_BF16(s8[np*2],   fqh[kk], bh4);
                    MMA_BF16(s8[np*2],   fqh[kk], bl4);
                    MMA_BF16(s8[np*2],   fql[kk], bh4);
                    MMA_BF16(s8[np*2+1], fqh[kk], bh4 + 2);
                    MMA_BF16(s8[np*2+1], fqh[kk], bl4 + 2);
                    MMA_BF16(s8[np*2+1], fql[kk], bh4 + 2);
                }
            }

            if (64 * c + 63 > q0 + w * 16) {
                #pragma unroll
                for (int t = 0; t < 8; t++) {
                    int col = c * 64 + t * 8 + (lane & 3) * 2;
                    if (col     > r0) s8[t][0] = -1e30f;
                    if (col + 1 > r0) s8[t][1] = -1e30f;
                    if (col     > r1) s8[t][2] = -1e30f;
                    if (col + 1 > r1) s8[t][3] = -1e30f;
                }
            }

            float mx0 = -1e30f, mx1 = -1e30f;
            #pragma unroll
            for (int t = 0; t < 8; t++) {
                mx0 = fmaxf(mx0, fmaxf(s8[t][0], s8[t][1]));
                mx1 = fmaxf(mx1, fmaxf(s8[t][2], s8[t][3]));
            }
            mx0 = fmaxf(mx0, __shfl_xor_sync(0xffffffffu, mx0, 1));
            mx0 = fmaxf(mx0, __shfl_xor_sync(0xffffffffu, mx0, 2));
            mx1 = fmaxf(mx1, __shfl_xor_sync(0xffffffffu, mx1, 1));
            mx1 = fmaxf(mx1, __shfl_xor_sync(0xffffffffu, mx1, 2));
            float mn0 = fmaxf(m0, mx0), mn1 = fmaxf(m1, mx1);
            float a0 = exp2f(m0 - mn0), a1 = exp2f(m1 - mn1);
            m0 = mn0;  m1 = mn1;
            float sum0 = 0.f, sum1 = 0.f;
            #pragma unroll
            for (int t = 0; t < 8; t++) {
                s8[t][0] = exp2f(s8[t][0] - mn0);
                s8[t][1] = exp2f(s8[t][1] - mn0);
                s8[t][2] = exp2f(s8[t][2] - mn1);
                s8[t][3] = exp2f(s8[t][3] - mn1);
                sum0 += s8[t][0] + s8[t][1];
                sum1 += s8[t][2] + s8[t][3];
            }
            l0 = l0 * a0 + sum0;
            l1 = l1 * a1 + sum1;
            #pragma unroll
            for (int nt = 0; nt < 16; nt++) {
                o[nt][0] *= a0;  o[nt][1] *= a0;
                o[nt][2] *= a1;  o[nt][3] *= a1;
            }

            #pragma unroll
            for (int kk2 = 0; kk2 < 4; kk2++) {
                uint32_t pah[4], pal[4];
                split2(s8[2*kk2][0],   s8[2*kk2][1],   pah[0], pal[0]);
                split2(s8[2*kk2][2],   s8[2*kk2][3],   pah[1], pal[1]);
                split2(s8[2*kk2+1][0], s8[2*kk2+1][1], pah[2], pal[2]);
                split2(s8[2*kk2+1][2], s8[2*kk2+1][3], pah[3], pal[3]);
                #pragma unroll
                for (int np = 0; np < 8; np++) {
                    uint32_t rv = st + 2 * FL_MAT
                                + (kk2 * 16 + (lane & 15)) * FL_STRIDE
                                + (np * 16 + (lane >> 4) * 8) * 2;
                    uint32_t vh4[4], vl4[4];
                    LDSM_T_X4(vh4, rv);
                    LDSM_T_X4(vl4, rv + FL_MAT);
                    MMA_BF16(o[np*2],   pah, vh4);
                    MMA_BF16(o[np*2],   pah, vl4);
                    MMA_BF16(o[np*2],   pal, vh4);
                    MMA_BF16(o[np*2+1], pah, vh4 + 2);
                    MMA_BF16(o[np*2+1], pah, vl4 + 2);
                    MMA_BF16(o[np*2+1], pal, vh4 + 2);
                }
            }
        }
        __syncthreads();
        if (c + 2 < C && tid == 0) {
            MBAR_EXPECT(mb0 + s * 8, (uint32_t)FL_STAGE);
            BULK_G2S(sb + s * FL_STAGE, kvbase + (size_t)(c + 2) * FL_STAGE,
                     (uint32_t)FL_STAGE, mb0 + s * 8);
        }
    }

    l0 += __shfl_xor_sync(0xffffffffu, l0, 1);
    l0 += __shfl_xor_sync(0xffffffffu, l0, 2);
    l1 += __shfl_xor_sync(0xffffffffu, l1, 1);
    l1 += __shfl_xor_sync(0xffffffffu, l1, 2);
    float inv0 = 1.0f / l0, inv1 = 1.0f / l1;

    const int gr0 = b * SEQ + r0;
    const int gr1 = b * SEQ + r1;
    #pragma unroll
    for (int nt = 0; nt < 16; nt++) {
        int colh = nt * 8 + (lane & 3) * 2;
        int c    = h * 4 + (colh >> 5);
        uint32_t inoff = ((uint32_t)(colh & 31) >> 3) * 16 + (colh & 7) * 2;
        uint32_t hi, lo;
        size_t b0 = ((size_t)((gr0 >> 7) * 64 + c)) * BLKB + (uint32_t)(gr0 & 127) * PADB + inoff;
        split2(o[nt][0] * inv0, o[nt][1] * inv0, hi, lo);
        *(uint32_t*)(apack + b0)        = hi;
        *(uint32_t*)(apack + b0 + AMAT) = lo;
        size_t b1 = ((size_t)((gr1 >> 7) * 64 + c)) * BLKB + (uint32_t)(gr1 & 127) * PADB + inoff;
        split2(o[nt][2] * inv1, o[nt][3] * inv1, hi, lo);
        *(uint32_t*)(apack + b1)        = hi;
        *(uint32_t*)(apack + b1 + AMAT) = lo;
    }
}

// ---------------------------------------------------------------------------
extern "C" void kernel_launch(void* const* d_in, const int* in_sizes, int n_in,
                              void* d_out, int out_size) {
    const float* x  = (const float*)d_in[0];
    const float* Wq = (const float*)d_in[1];
    const float* Wk = (const float*)d_in[2];
    const float* Wv = (const float*)d_in[3];
    const float* Wo = (const float*)d_in[4];
    float* out = (float*)d_out;

    float *qp, *kp, *vp;
    cudaGetSymbolAddress((void**)&qp, g_q);
    cudaGetSymbolAddress((void**)&kp, g_k);
    cudaGetSymbolAddress((void**)&vp, g_v);

    unsigned char *xpk, *apk, *wpk, *qpk, *kvpk;
    cudaGetSymbolAddress((void**)&xpk, g_xpack);
    cudaGetSymbolAddress((void**)&apk, g_apack);
    cudaGetSymbolAddress((void**)&wpk, g_wpack);
    cudaGetSymbolAddress((void**)&qpk, g_qpack);
    cudaGetSymbolAddress((void**)&kvpk, g_kvpack);

    cudaFuncSetAttribute(gemm_hmma, cudaFuncAttributeMaxDynamicSharedMemorySize, GEMM_SMEM);
    cudaFuncSetAttribute(flash_hmma, cudaFuncAttributeMaxDynamicSharedMemorySize, FL_SMEM);

    // pack all weights and x
    {
        dim3 tb(32, 8), tg(D_MODEL / 32, D_MODEL / 32);
        split_t_pack<<<tg, tb>>>(Wq, wpk, 0);
        split_t_pack<<<tg, tb>>>(Wk, wpk, 16);
        split_t_pack<<<tg, tb>>>(Wv, wpk, 32);
        split_t_pack<<<tg, tb>>>(Wo, wpk, 48);   // hoisted: done before flash
        int n8 = MROWS * D_MODEL / 8;
        split_e_pack<<<(n8 + 255) / 256, 256>>>(x, xpk);
    }

    // fused QKV projection
    {
        dim3 ggrid(48, MROWS / 128);   // (48, 32)
        gemm_hmma<<<ggrid, 256, GEMM_SMEM>>>(xpk, wpk, 0, qp, kp, vp);
    }

    {
        int total = MROWS * NHEAD * (HD / 2);
        rope_split<<<(total + 255) / 256, 256>>>(qp, kp, vp, qpk, kvpk);
    }

    {
        dim3 fgrid(SEQ / 128, BATCH * NHEAD);  // (16, 32)
        flash_hmma<<<fgrid, 256, FL_SMEM>>>(qpk, kvpk, apk);
    }

    // output projection
    {
        dim3 ggrid(16, MROWS / 128);   // (16, 32)
        gemm_hmma<<<ggrid, 256, GEMM_SMEM>>>(apk, wpk, 48, out, out, out);
    }
}